// round 12
// baseline (speedup 1.0000x reference)
#include <cuda_runtime.h>
#include <cstdint>

#define B_  8
#define H_  128
#define W_  128
#define C_  64
#define F_  128

#define SA2 72    // A smem stride: banks (tc*8+g) -> conflict-free frags
#define SB  136   // B smem stride: banks (tc*8+g) -> conflict-free frags
#define BBUF (32*SB)                        // 4352 floats per B chunk (padded)
#define ABUF (32*SA2)                       // 2304 floats

// scratch
__device__ float  g_offsets[B_*H_*W_*18];   // predicted offsets [B,H,W,18]
__device__ float  g_wTp[18*BBUF];           // w_out tf32, pre-padded [ch][kk*SB+n]
__device__ float2 g_wOff2[3*3*64*10];       // w_off as oc-pairs [dydx][c][10]
__device__ float4 g_xT[B_*16*H_*W_];        // x channel-blocked [b][c/4][y][x]

__device__ __forceinline__ uint32_t f2tf32(float f){
    uint32_t r; asm("cvt.rna.tf32.f32 %0, %1;" : "=r"(r) : "f"(f)); return r;
}
__device__ __forceinline__ unsigned long long pack2(float x, float y){
    unsigned long long r;
    asm("mov.b64 %0, {%1,%2};" : "=l"(r) : "f"(x), "f"(y));
    return r;
}
__device__ __forceinline__ void ffma2(unsigned long long& acc,
                                      unsigned long long a, unsigned long long w){
    asm("fma.rn.f32x2 %0, %1, %2, %0;" : "+l"(acc) : "l"(a), "l"(w));
}
__device__ __forceinline__ void addf2(unsigned long long& acc, unsigned long long v){
    asm("add.rn.f32x2 %0, %1, %2;" : "=l"(acc) : "l"(acc), "l"(v));
}
__device__ __forceinline__ uint32_t smem_u32(const void* p){
    uint32_t a;
    asm("{ .reg .u64 t; cvta.to.shared.u64 t, %1; cvt.u32.u64 %0, t; }":"=r"(a):"l"(p));
    return a;
}
__device__ __forceinline__ void cpasync16(uint32_t dst, const void* src){
    asm volatile("cp.async.cg.shared.global [%0], [%1], 16;"::"r"(dst),"l"(src):"memory");
}
#define CP_COMMIT() asm volatile("cp.async.commit_group;":::"memory")
#define CP_WAIT0()  asm volatile("cp.async.wait_group 0;":::"memory")

__device__ __forceinline__ void mma_tf32(float* d, const uint32_t* a, const uint32_t* bb){
    asm volatile(
      "mma.sync.aligned.m16n8k8.row.col.f32.tf32.tf32.f32 "
      "{%0,%1,%2,%3}, {%4,%5,%6,%7}, {%8,%9}, {%0,%1,%2,%3};"
      : "+f"(d[0]),"+f"(d[1]),"+f"(d[2]),"+f"(d[3])
      : "r"(a[0]),"r"(a[1]),"r"(a[2]),"r"(a[3]),"r"(bb[0]),"r"(bb[1]));
}

// ---------------------------------------------------------------------------
// Prep kernels (unchanged)
// ---------------------------------------------------------------------------
__global__ void prep_wp_kernel(const float* __restrict__ w_out)
{
    int idx = blockIdx.x * 256 + threadIdx.x;   // 18*BBUF = 78336
    if (idx >= 18*BBUF) return;
    int n  = idx % SB;
    int kk = (idx / SB) & 31;
    int ch = idx / BBUF;
    float v = 0.f;
    if (n < 128) v = __uint_as_float(f2tf32(w_out[(ch*32 + kk)*128 + n]));
    g_wTp[idx] = v;
}
__global__ void prep_woff2_kernel(const float* __restrict__ w_off)
{
    int idx = blockIdx.x * 256 + threadIdx.x;   // 5760
    if (idx >= 5760) return;
    int p    = idx % 10;
    int c    = (idx / 10) % 64;
    int dydx = idx / 640;
    float2 v = make_float2(0.f, 0.f);
    if (p < 9) {
        v.x = w_off[(dydx*64 + c)*18 + 2*p];
        v.y = w_off[(dydx*64 + c)*18 + 2*p + 1];
    }
    g_wOff2[idx] = v;
}
__global__ __launch_bounds__(256) void transpose_x(const float4* __restrict__ x4)
{
    const int blk  = blockIdx.x;
    const int px   = threadIdx.x & 127;
    const int half = threadIdx.x >> 7;
    const int b = blk >> 7, y = blk & 127;
    const int pix16 = (blk * 128 + px) * 16;
    #pragma unroll
    for (int q = 0; q < 8; q++) {
        int cb = half * 8 + q;
        g_xT[((b*16 + cb) << 14) + y*128 + px] = x4[pix16 + cb];
    }
}

// ---------------------------------------------------------------------------
// Kernel 1: 3x3 SAME conv 64->18, fp32 f32x2.
// TWO output rows per block: each weight load feeds 2 ffma2 (rows y, y+1).
// Weights loaded as uniform ulonglong2 (LDS.128). th splits channel halves.
// ---------------------------------------------------------------------------
#define ROWF   (130*66)
#define WSLICE (3*64*10)                        // u64 per dy slice
#define SM1_TOTAL (2*ROWF*4 + WSLICE*8)         // 84000 B

__global__ __launch_bounds__(256) void offset_conv_kernel(
    const float* __restrict__ x, const float* __restrict__ b_off)
{
    extern __shared__ float sm1[];
    float* rows0 = sm1;                         // input row for out y (at dy)
    float* rows1 = sm1 + ROWF;                  // input row for out y+1
    unsigned long long* wsh = (unsigned long long*)(sm1 + 2*ROWF);

    const int t  = threadIdx.x;
    const int pm = t & 127;
    const int th = t >> 7;                 // channel half: 0 -> c<32, 1 -> c>=32
    const int by = blockIdx.x;             // 0..511
    const int b  = by >> 6;
    const int y  = (by & 63) << 1;

    unsigned long long acc[2][9];
    #pragma unroll
    for (int p = 0; p < 9; p++) {
        unsigned long long bz = th ? pack2(0.f, 0.f)
                                   : pack2(b_off[2*p], b_off[2*p+1]);
        acc[0][p] = bz;  acc[1][p] = bz;
    }

    for (int dy = 0; dy < 3; dy++) {
        __syncthreads();                   // protect previous iter's reads
        // stage this dy's weight slice
        {
            const unsigned long long* src =
                (const unsigned long long*)g_wOff2 + dy * WSLICE;
            for (int i = t; i < WSLICE; i += 256) wsh[i] = src[i];
        }
        // stage two input rows: th=0 -> (y+dy-1), th=1 -> (y+dy)
        {
            const int yy = y + dy - 1 + th;
            float* dstb = th ? rows1 : rows0;
            if (pm < 2) {
                const int e = (pm == 0) ? 0 : 129;
                float2* z = (float2*)&dstb[e * 66];
                #pragma unroll
                for (int i = 0; i < 32; i++) z[i] = make_float2(0.f, 0.f);
            }
            float2* dst = (float2*)&dstb[(pm + 1) * 66];
            if ((unsigned)yy < 128u) {
                const float4* src =
                    (const float4*)&x[((b * H_ + yy) * W_ + pm) * C_];
                #pragma unroll
                for (int i = 0; i < 16; i++) {
                    float4 v = src[i];
                    dst[2*i]   = make_float2(v.x, v.y);
                    dst[2*i+1] = make_float2(v.z, v.w);
                }
            } else {
                #pragma unroll
                for (int i = 0; i < 32; i++) dst[i] = make_float2(0.f, 0.f);
            }
        }
        __syncthreads();

        #pragma unroll
        for (int dx = 0; dx < 3; dx++) {
            const float* r0 = &rows0[(pm + dx) * 66 + th * 32];
            const float* r1 = &rows1[(pm + dx) * 66 + th * 32];
            const unsigned long long* wdx = wsh + dx * 640 + th * 320;
            #pragma unroll 2
            for (int c = 0; c < 32; c += 2) {
                const float2 v0 = *(const float2*)&r0[c];
                const float2 v1 = *(const float2*)&r1[c];
                const ulonglong2* wx2 = (const ulonglong2*)(wdx + c * 10);
                const ulonglong2* wy2 = wx2 + 5;

                const unsigned long long ax0 = pack2(v0.x, v0.x);
                const unsigned long long ax1 = pack2(v1.x, v1.x);
                {
                    ulonglong2 wv[5];
                    #pragma unroll
                    for (int q = 0; q < 5; q++) wv[q] = wx2[q];
                    const unsigned long long* w = (const unsigned long long*)wv;
                    #pragma unroll
                    for (int p = 0; p < 9; p++) {
                        ffma2(acc[0][p], ax0, w[p]);
                        ffma2(acc[1][p], ax1, w[p]);
                    }
                }
                const unsigned long long ay0 = pack2(v0.y, v0.y);
                const unsigned long long ay1 = pack2(v1.y, v1.y);
                {
                    ulonglong2 wv[5];
                    #pragma unroll
                    for (int q = 0; q < 5; q++) wv[q] = wy2[q];
                    const unsigned long long* w = (const unsigned long long*)wv;
                    #pragma unroll
                    for (int p = 0; p < 9; p++) {
                        ffma2(acc[0][p], ay0, w[p]);
                        ffma2(acc[1][p], ay1, w[p]);
                    }
                }
            }
        }
    }

    // cross-half reduction (reuse row area)
    __syncthreads();
    unsigned long long* red = (unsigned long long*)sm1;   // 128*18 u64
    if (th == 1) {
        #pragma unroll
        for (int r = 0; r < 2; r++)
            #pragma unroll
            for (int p = 0; p < 9; p++)
                red[(pm * 2 + r) * 9 + p] = acc[r][p];
    }
    __syncthreads();
    if (th == 0) {
        #pragma unroll
        for (int r = 0; r < 2; r++) {
            float2* op = (float2*)&g_offsets[((b * H_ + y + r) * W_ + pm) * 18];
            #pragma unroll
            for (int p = 0; p < 9; p++) {
                addf2(acc[r][p], red[(pm * 2 + r) * 9 + p]);
                float lo, hi;
                asm("mov.b64 {%0,%1}, %2;" : "=f"(lo), "=f"(hi) : "l"(acc[r][p]));
                op[p] = make_float2(lo, hi);
            }
        }
    }
}

// ---------------------------------------------------------------------------
// Kernel 2: fused bilinear sampling + tf32 mma GEMM (round-11, unchanged)
// ---------------------------------------------------------------------------
#define SM2_TOTAL ((2*ABUF + 2*BBUF)*4)     // 53248 B

__global__ __launch_bounds__(256, 2) void dconv_gemm_mma(
    const float* __restrict__ b_out, float* __restrict__ out)
{
    extern __shared__ float sm[];
    float* Abuf[2] = { sm, sm + ABUF };
    float* Bbuf[2] = { sm + 2*ABUF, sm + 2*ABUF + BBUF };
    const uint32_t Bu = smem_u32(sm + 2*ABUF);

    const int tid  = threadIdx.x;
    const int wid  = tid >> 5;
    const int lane = tid & 31;
    const int g  = lane >> 2;
    const int tc = lane & 3;

    const int p0 = blockIdx.x * 64;
    const int b  = p0 >> 14;
    const int y  = (p0 >> 7) & 127;
    const int x0 = p0 & 127;
    const int pm = tid & 63;
    const int h  = tid >> 6;
    const int gx = x0 + pm;

    const int m_base = (wid >> 2) * 32;
    const int n_base = (wid & 3) * 32;
    const float* offp = &g_offsets[(p0 + pm) * 18];

    float acc[2][4][4];
    #pragma unroll
    for (int nf = 0; nf < 4; nf++) {
        const int c0 = n_base + nf*8 + 2*tc;
        const float bz0 = __ldg(&b_out[c0]), bz1 = __ldg(&b_out[c0+1]);
        #pragma unroll
        for (int mf = 0; mf < 2; mf++) {
            acc[mf][nf][0] = bz0; acc[mf][nf][1] = bz1;
            acc[mf][nf][2] = bz0; acc[mf][nf][3] = bz1;
        }
    }

    float wa=0.f, wbv=0.f, wcv=0.f, wdv=0.f;
    int i00=0, i10=0, i01=0, i11=0;

    #define COORDS(off) { \
        float nx = fminf(fmaxf((float)gx + (off).x, 0.f), 127.f); \
        float ny = fminf(fmaxf((float)y  + (off).y, 0.f), 127.f); \
        float x0f = floorf(nx), y0f = floorf(ny); \
        float x1f = fminf(x0f + 1.f, 127.f), y1f = fminf(y0f + 1.f, 127.f); \
        float lx = nx - x0f, hx = x1f - nx; \
        float ly = ny - y0f, hy = y1f - ny; \
        wa = hx*hy; wbv = hx*ly; wcv = lx*hy; wdv = lx*ly; \
        int ix0 = (int)x0f, ix1 = (int)x1f, iy0 = (int)y0f, iy1 = (int)y1f; \
        i00 = iy0*128 + ix0;  i10 = iy1*128 + ix0; \
        i01 = iy0*128 + ix1;  i11 = iy1*128 + ix1; }

    float4 a0,b0,c0_,d0, a1,b1,c1_,d1;
    uint32_t vv[8];

    #define GATHER2(chv) { \
        const int cb = (b*16 + ((chv)&1)*8 + h*2) << 14; \
        a0 = g_xT[cb + i00]; b0 = g_xT[cb + i10]; \
        c0_ = g_xT[cb + i01]; d0 = g_xT[cb + i11]; \
        const int cb1 = cb + (1 << 14); \
        a1 = g_xT[cb1 + i00]; b1 = g_xT[cb1 + i10]; \
        c1_ = g_xT[cb1 + i01]; d1 = g_xT[cb1 + i11]; }

    #define WEIGHT2() { \
        vv[0] = f2tf32(wa*a0.x + wbv*b0.x + wcv*c0_.x + wdv*d0.x); \
        vv[1] = f2tf32(wa*a0.y + wbv*b0.y + wcv*c0_.y + wdv*d0.y); \
        vv[2] = f2tf32(wa*a0.z + wbv*b0.z + wcv*c0_.z + wdv*d0.z); \
        vv[3] = f2tf32(wa*a0.w + wbv*b0.w + wcv*c0_.w + wdv*d0.w); \
        vv[4] = f2tf32(wa*a1.x + wbv*b1.x + wcv*c1_.x + wdv*d1.x); \
        vv[5] = f2tf32(wa*a1.y + wbv*b1.y + wcv*c1_.y + wdv*d1.y); \
        vv[6] = f2tf32(wa*a1.z + wbv*b1.z + wcv*c1_.z + wdv*d1.z); \
        vv[7] = f2tf32(wa*a1.w + wbv*b1.w + wcv*c1_.w + wdv*d1.w); }

    #define CPB(chv, pbuf) { \
        const uint32_t dbase = Bu + (uint32_t)(pbuf) * (BBUF*4u); \
        const char* srcb = (const char*)&g_wTp[(chv) * BBUF]; \
        _Pragma("unroll") \
        for (int i = 0; i < 5; i++) { \
            int idx = tid + i*256; \
            if (idx < 1088) cpasync16(dbase + (uint32_t)idx*16u, srcb + idx*16); \
        } }

    #define MMASTEP(s, Ab, Bb) { \
        const int k0 = (s) * 8; \
        const uint32_t* Ar0 = (const uint32_t*)&(Ab)[(k0 + tc)     * SA2]; \
        const uint32_t* Ar1 = (const uint32_t*)&(Ab)[(k0 + tc + 4) * SA2]; \
        const uint32_t* Br0 = (const uint32_t*)&(Bb)[(k0 + tc)     * SB]; \
        const uint32_t* Br1 = (const uint32_t*)&(Bb)[(k0 + tc + 4) * SB]; \
        uint32_t afr[2][4]; \
        _Pragma("unroll") \
        for (int mf = 0; mf < 2; mf++) { \
            const int m = m_base + mf*16 + g; \
            afr[mf][0] = Ar0[m];  afr[mf][1] = Ar0[m+8]; \
            afr[mf][2] = Ar1[m];  afr[mf][3] = Ar1[m+8]; \
        } \
        uint32_t bfr[4][2]; \
        _Pragma("unroll") \
        for (int nf = 0; nf < 4; nf++) { \
            const int n = n_base + nf*8 + g; \
            bfr[nf][0] = Br0[n];  bfr[nf][1] = Br1[n]; \
        } \
        _Pragma("unroll") \
        for (int mf = 0; mf < 2; mf++) \
            _Pragma("unroll") \
            for (int nf = 0; nf < 4; nf++) \
                mma_tf32(acc[mf][nf], afr[mf], bfr[nf]); }

    // ---- prologue ----
    float2 curoff  = *(const float2*)(offp + 0);
    float2 nextoff = *(const float2*)(offp + 2);
    COORDS(curoff);
    GATHER2(0);
    WEIGHT2();
    CPB(0, 0); CP_COMMIT();

    for (int ch = 0; ch < 18; ch++) {
        const int p = ch & 1;
        float* Ab = Abuf[p];
        float* Bb = Bbuf[p];

        #pragma unroll
        for (int j = 0; j < 2; j++) {
            const int k = h*8 + j*4;
            Ab[(k+0)*SA2 + pm] = __uint_as_float(vv[j*4+0]);
            Ab[(k+1)*SA2 + pm] = __uint_as_float(vv[j*4+1]);
            Ab[(k+2)*SA2 + pm] = __uint_as_float(vv[j*4+2]);
            Ab[(k+3)*SA2 + pm] = __uint_as_float(vv[j*4+3]);
        }

        CP_WAIT0();
        __syncthreads();

        const bool more = (ch + 1 < 18);
        if (more) {
            if (((ch + 1) & 1) == 0) {
                COORDS(nextoff);
                if (ch + 1 <= 14)
                    nextoff = *(const float2*)(offp + ((ch+3) >> 1) * 2);
            }
            GATHER2(ch + 1);
            CPB(ch + 1, p ^ 1); CP_COMMIT();
        }

        MMASTEP(0, Ab, Bb);
        MMASTEP(1, Ab, Bb);
        MMASTEP(2, Ab, Bb);
        MMASTEP(3, Ab, Bb);

        if (more) { WEIGHT2(); }
    }

    #pragma unroll
    for (int mf = 0; mf < 2; mf++) {
        const int row = p0 + m_base + mf*16 + g;
        #pragma unroll
        for (int nf = 0; nf < 4; nf++) {
            const int col = n_base + nf*8 + 2*tc;
            *(float2*)&out[(size_t)row * F_ + col] =
                make_float2(acc[mf][nf][0], acc[mf][nf][1]);
            *(float2*)&out[(size_t)(row + 8) * F_ + col] =
                make_float2(acc[mf][nf][2], acc[mf][nf][3]);
        }
    }
}

// ---------------------------------------------------------------------------
extern "C" void kernel_launch(void* const* d_in, const int* in_sizes, int n_in,
                              void* d_out, int out_size)
{
    const float* x     = (const float*)d_in[0];
    const float* w_off = (const float*)d_in[1];
    const float* b_off = (const float*)d_in[2];
    const float* w_out = (const float*)d_in[3];
    const float* b_out = (const float*)d_in[4];
    float* out = (float*)d_out;

    cudaFuncSetAttribute(offset_conv_kernel,
                         cudaFuncAttributeMaxDynamicSharedMemorySize, SM1_TOTAL);
    cudaFuncSetAttribute(dconv_gemm_mma,
                         cudaFuncAttributeMaxDynamicSharedMemorySize, SM2_TOTAL);

    prep_wp_kernel    <<<(18*BBUF + 255)/256, 256>>>(w_out);
    prep_woff2_kernel <<<(5760 + 255)/256, 256>>>(w_off);
    transpose_x       <<<B_ * H_, 256>>>((const float4*)x);
    offset_conv_kernel<<<B_ * 64, 256, SM1_TOTAL>>>(x, b_off);
    dconv_gemm_mma    <<<(B_*H_*W_)/64, 256, SM2_TOTAL>>>(b_out, out);
}

// round 13
// speedup vs baseline: 1.2291x; 1.2291x over previous
#include <cuda_runtime.h>
#include <cstdint>

#define B_  8
#define H_  128
#define W_  128
#define C_  64
#define F_  128

#define SB   136  // B smem stride: banks (tc*8+g) -> conflict-free frags
#define SA3  136  // A smem stride (128 px + 8 pad), same conflict-free property
#define BBUF (32*SB)                        // 4352 floats
#define ABUF2 (32*SA3)                      // 4352 floats

// scratch
__device__ float  g_offsets[B_*H_*W_*18];   // predicted offsets [B,H,W,18]
__device__ float  g_wTp[18*BBUF];           // w_out tf32, pre-padded [ch][kk*SB+n]
__device__ float2 g_wOff2[3*3*64*10];       // w_off as oc-pairs [dydx][c][10]
__device__ float4 g_xT[B_*16*H_*W_];        // x channel-blocked [b][c/4][y][x]

__device__ __forceinline__ uint32_t f2tf32(float f){
    uint32_t r; asm("cvt.rna.tf32.f32 %0, %1;" : "=r"(r) : "f"(f)); return r;
}
__device__ __forceinline__ unsigned long long pack2(float x, float y){
    unsigned long long r;
    asm("mov.b64 %0, {%1,%2};" : "=l"(r) : "f"(x), "f"(y));
    return r;
}
__device__ __forceinline__ void ffma2(unsigned long long& acc,
                                      unsigned long long a, unsigned long long w){
    asm("fma.rn.f32x2 %0, %1, %2, %0;" : "+l"(acc) : "l"(a), "l"(w));
}
__device__ __forceinline__ void addf2(unsigned long long& acc, unsigned long long v){
    asm("add.rn.f32x2 %0, %1, %2;" : "=l"(acc) : "l"(acc), "l"(v));
}
__device__ __forceinline__ uint32_t smem_u32(const void* p){
    uint32_t a;
    asm("{ .reg .u64 t; cvta.to.shared.u64 t, %1; cvt.u32.u64 %0, t; }":"=r"(a):"l"(p));
    return a;
}
__device__ __forceinline__ void cpasync16(uint32_t dst, const void* src){
    asm volatile("cp.async.cg.shared.global [%0], [%1], 16;"::"r"(dst),"l"(src):"memory");
}
#define CP_COMMIT() asm volatile("cp.async.commit_group;":::"memory")
#define CP_WAIT0()  asm volatile("cp.async.wait_group 0;":::"memory")

__device__ __forceinline__ void mma_tf32(float* d, const uint32_t* a, const uint32_t* bb){
    asm volatile(
      "mma.sync.aligned.m16n8k8.row.col.f32.tf32.tf32.f32 "
      "{%0,%1,%2,%3}, {%4,%5,%6,%7}, {%8,%9}, {%0,%1,%2,%3};"
      : "+f"(d[0]),"+f"(d[1]),"+f"(d[2]),"+f"(d[3])
      : "r"(a[0]),"r"(a[1]),"r"(a[2]),"r"(a[3]),"r"(bb[0]),"r"(bb[1]));
}

// ---------------------------------------------------------------------------
// Prep kernels (unchanged)
// ---------------------------------------------------------------------------
__global__ void prep_wp_kernel(const float* __restrict__ w_out)
{
    int idx = blockIdx.x * 256 + threadIdx.x;   // 18*BBUF = 78336
    if (idx >= 18*BBUF) return;
    int n  = idx % SB;
    int kk = (idx / SB) & 31;
    int ch = idx / BBUF;
    float v = 0.f;
    if (n < 128) v = __uint_as_float(f2tf32(w_out[(ch*32 + kk)*128 + n]));
    g_wTp[idx] = v;
}
__global__ void prep_woff2_kernel(const float* __restrict__ w_off)
{
    int idx = blockIdx.x * 256 + threadIdx.x;   // 5760
    if (idx >= 5760) return;
    int p    = idx % 10;
    int c    = (idx / 10) % 64;
    int dydx = idx / 640;
    float2 v = make_float2(0.f, 0.f);
    if (p < 9) {
        v.x = w_off[(dydx*64 + c)*18 + 2*p];
        v.y = w_off[(dydx*64 + c)*18 + 2*p + 1];
    }
    g_wOff2[idx] = v;
}
__global__ __launch_bounds__(256) void transpose_x(const float4* __restrict__ x4)
{
    const int blk  = blockIdx.x;
    const int px   = threadIdx.x & 127;
    const int half = threadIdx.x >> 7;
    const int b = blk >> 7, y = blk & 127;
    const int pix16 = (blk * 128 + px) * 16;
    #pragma unroll
    for (int q = 0; q < 8; q++) {
        int cb = half * 8 + q;
        g_xT[((b*16 + cb) << 14) + y*128 + px] = x4[pix16 + cb];
    }
}

// ---------------------------------------------------------------------------
// Kernel 1: round-11 proven version (118us). fp32 f32x2, channel-split,
// per-dy weight staging (49.7 KB smem -> 4 blocks/SM).
// ---------------------------------------------------------------------------
#define ROWF   (130*66)
#define WSLICE (3*64*10)
#define SM1_TOTAL ((ROWF + WSLICE*2) * 4)       // 49680 B

__global__ __launch_bounds__(256) void offset_conv_kernel(
    const float* __restrict__ x, const float* __restrict__ b_off)
{
    extern __shared__ float sm1[];
    float* row = sm1;
    unsigned long long* wsh = (unsigned long long*)(sm1 + ROWF);

    const int t  = threadIdx.x;
    const int pm = t & 127;
    const int th = t >> 7;
    const int by = blockIdx.x;
    const int b  = by >> 7;
    const int y  = by & 127;

    unsigned long long acc[9];
    #pragma unroll
    for (int p = 0; p < 9; p++)
        acc[p] = th ? pack2(0.f, 0.f) : pack2(b_off[2*p], b_off[2*p+1]);

    for (int dy = 0; dy < 3; dy++) {
        __syncthreads();
        const int yy = y + dy - 1;
        {
            const unsigned long long* src =
                (const unsigned long long*)g_wOff2 + dy * WSLICE;
            for (int i = t; i < WSLICE; i += 256) wsh[i] = src[i];
        }
        if (t < 2) {
            const int e = (t == 0) ? 0 : 129;
            float2* z = (float2*)&row[e * 66];
            #pragma unroll
            for (int i = 0; i < 32; i++) z[i] = make_float2(0.f, 0.f);
        }
        {
            float2* dst = (float2*)&row[(pm + 1) * 66] + th * 16;
            if (yy >= 0 && yy < 128) {
                const float4* src =
                    (const float4*)&x[((b * H_ + yy) * W_ + pm) * C_ + th * 32];
                #pragma unroll
                for (int i = 0; i < 8; i++) {
                    float4 v = src[i];
                    dst[2*i]   = make_float2(v.x, v.y);
                    dst[2*i+1] = make_float2(v.z, v.w);
                }
            } else {
                #pragma unroll
                for (int i = 0; i < 16; i++) dst[i] = make_float2(0.f, 0.f);
            }
        }
        __syncthreads();

        #pragma unroll
        for (int dx = 0; dx < 3; dx++) {
            const float* rowp = &row[(pm + dx) * 66 + th * 32];
            const unsigned long long* wdx = wsh + dx * 640 + th * 320;
            #pragma unroll 4
            for (int c = 0; c < 32; c += 2) {
                const float2 rv = *(const float2*)&rowp[c];
                const unsigned long long ax = pack2(rv.x, rv.x);
                const unsigned long long ay = pack2(rv.y, rv.y);
                const unsigned long long* wx = wdx + c * 10;
                const unsigned long long* wy = wx + 10;
                #pragma unroll
                for (int p = 0; p < 9; p++) ffma2(acc[p], ax, wx[p]);
                #pragma unroll
                for (int p = 0; p < 9; p++) ffma2(acc[p], ay, wy[p]);
            }
        }
    }

    __syncthreads();
    unsigned long long* red = (unsigned long long*)row;
    if (th == 1) {
        #pragma unroll
        for (int p = 0; p < 9; p++) red[pm*10 + p] = acc[p];
    }
    __syncthreads();
    if (th == 0) {
        float2* op = (float2*)&g_offsets[((b * H_ + y) * W_ + pm) * 18];
        #pragma unroll
        for (int p = 0; p < 9; p++) {
            addf2(acc[p], red[pm*10 + p]);
            float lo, hi;
            asm("mov.b64 {%0,%1}, %2;" : "=f"(lo), "=f"(hi) : "l"(acc[p]));
            op[p] = make_float2(lo, hi);
        }
    }
}

// ---------------------------------------------------------------------------
// Kernel 2: fused sampling + tf32 mma GEMM, M=128 tile, dual m-subtiles.
// 256 thr = 8 warps (2m x 4n of 32x32) x 2 m-subtiles -> B frags reused 2x.
// A-gen: 2 thr/px, 4 planes each, interleaved per-plane with MMA k-steps.
// ---------------------------------------------------------------------------
#define SM2_TOTAL ((2*ABUF2 + 2*BBUF)*4)    // 69632 B -> 2 blocks/SM

__global__ __launch_bounds__(256, 2) void dconv_gemm_mma(
    const float* __restrict__ b_out, float* __restrict__ out)
{
    extern __shared__ float sm[];
    float* Abuf[2] = { sm, sm + ABUF2 };
    float* Bbuf[2] = { sm + 2*ABUF2, sm + 2*ABUF2 + BBUF };
    const uint32_t Bu = smem_u32(sm + 2*ABUF2);

    const int tid  = threadIdx.x;
    const int wid  = tid >> 5;
    const int lane = tid & 31;
    const int g  = lane >> 2;
    const int tc = lane & 3;

    const int p0 = blockIdx.x * 128;      // full image row
    const int b  = p0 >> 14;
    const int y  = (p0 >> 7) & 127;
    const int pm = tid & 127;             // pixel in tile (= x coord)
    const int h  = tid >> 7;              // 0/1: 16-channel half

    const int m_base = (wid >> 2) * 32;
    const int n_base = (wid & 3) * 32;
    const float* offp = &g_offsets[(p0 + pm) * 18];

    float acc[2][2][4][4];                // [sub][mf][nf][reg]
    #pragma unroll
    for (int nf = 0; nf < 4; nf++) {
        const int c0 = n_base + nf*8 + 2*tc;
        const float bz0 = __ldg(&b_out[c0]), bz1 = __ldg(&b_out[c0+1]);
        #pragma unroll
        for (int sub = 0; sub < 2; sub++)
            #pragma unroll
            for (int mf = 0; mf < 2; mf++) {
                acc[sub][mf][nf][0] = bz0; acc[sub][mf][nf][1] = bz1;
                acc[sub][mf][nf][2] = bz0; acc[sub][mf][nf][3] = bz1;
            }
    }

    float wa=0.f, wbv=0.f, wcv=0.f, wdv=0.f;
    int i00=0, i10=0, i01=0, i11=0;

    #define COORDS(off) { \
        float nx = fminf(fmaxf((float)pm + (off).x, 0.f), 127.f); \
        float ny = fminf(fmaxf((float)y  + (off).y, 0.f), 127.f); \
        float x0f = floorf(nx), y0f = floorf(ny); \
        float x1f = fminf(x0f + 1.f, 127.f), y1f = fminf(y0f + 1.f, 127.f); \
        float lx = nx - x0f, hx = x1f - nx; \
        float ly = ny - y0f, hy = y1f - ny; \
        wa = hx*hy; wbv = hx*ly; wcv = lx*hy; wdv = lx*ly; \
        int ix0 = (int)x0f, ix1 = (int)x1f, iy0 = (int)y0f, iy1 = (int)y1f; \
        i00 = iy0*128 + ix0;  i10 = iy1*128 + ix0; \
        i01 = iy0*128 + ix1;  i11 = iy1*128 + ix1; }

    float4 ca, cb2, cc2, cd;              // one plane of corners (16 regs)

    #define GATHERPL(chv, j) { \
        const int cbp = (b*16 + ((chv)&1)*8 + h*4 + (j)) << 14; \
        ca  = g_xT[cbp + i00]; cb2 = g_xT[cbp + i10]; \
        cc2 = g_xT[cbp + i01]; cd  = g_xT[cbp + i11]; }

    // weight plane j and store straight to smem rows h*16 + j*4 + c
    #define WEIGHTSTS(j, Ab) { \
        const int kb = h*16 + (j)*4; \
        (Ab)[(kb+0)*SA3 + pm] = __uint_as_float(f2tf32(wa*ca.x + wbv*cb2.x + wcv*cc2.x + wdv*cd.x)); \
        (Ab)[(kb+1)*SA3 + pm] = __uint_as_float(f2tf32(wa*ca.y + wbv*cb2.y + wcv*cc2.y + wdv*cd.y)); \
        (Ab)[(kb+2)*SA3 + pm] = __uint_as_float(f2tf32(wa*ca.z + wbv*cb2.z + wcv*cc2.z + wdv*cd.z)); \
        (Ab)[(kb+3)*SA3 + pm] = __uint_as_float(f2tf32(wa*ca.w + wbv*cb2.w + wcv*cc2.w + wdv*cd.w)); }

    #define CPB(chv, pbuf) { \
        const uint32_t dbase = Bu + (uint32_t)(pbuf) * (BBUF*4u); \
        const char* srcb = (const char*)&g_wTp[(chv) * BBUF]; \
        _Pragma("unroll") \
        for (int i = 0; i < 5; i++) { \
            int idx = tid + i*256; \
            if (idx < 1088) cpasync16(dbase + (uint32_t)idx*16u, srcb + idx*16); \
        } }

    // one k-step: B frags loaded once, reused by both m-subtiles
    #define MMAS(s, Ab, Bb) { \
        const int k0 = (s) * 8; \
        const uint32_t* Br0 = (const uint32_t*)&(Bb)[(k0 + tc)     * SB]; \
        const uint32_t* Br1 = (const uint32_t*)&(Bb)[(k0 + tc + 4) * SB]; \
        uint32_t bfr[4][2]; \
        _Pragma("unroll") \
        for (int nf = 0; nf < 4; nf++) { \
            const int n = n_base + nf*8 + g; \
            bfr[nf][0] = Br0[n];  bfr[nf][1] = Br1[n]; \
        } \
        const uint32_t* Ar0 = (const uint32_t*)&(Ab)[(k0 + tc)     * SA3]; \
        const uint32_t* Ar1 = (const uint32_t*)&(Ab)[(k0 + tc + 4) * SA3]; \
        _Pragma("unroll") \
        for (int sub = 0; sub < 2; sub++) { \
            uint32_t afr[2][4]; \
            _Pragma("unroll") \
            for (int mf = 0; mf < 2; mf++) { \
                const int m = sub*64 + m_base + mf*16 + g; \
                afr[mf][0] = Ar0[m];  afr[mf][1] = Ar0[m+8]; \
                afr[mf][2] = Ar1[m];  afr[mf][3] = Ar1[m+8]; \
            } \
            _Pragma("unroll") \
            for (int mf = 0; mf < 2; mf++) \
                _Pragma("unroll") \
                for (int nf = 0; nf < 4; nf++) \
                    mma_tf32(acc[sub][mf][nf], afr[mf], bfr[nf]); \
        } }

    // ---- prologue: build A(0) into Abuf[0], start B(0) ----
    float2 curoff  = *(const float2*)(offp + 0);
    float2 nextoff = *(const float2*)(offp + 2);
    COORDS(curoff);
    #pragma unroll
    for (int j = 0; j < 4; j++) {
        GATHERPL(0, j);
        WEIGHTSTS(j, Abuf[0]);
    }
    CPB(0, 0); CP_COMMIT();

    for (int ch = 0; ch < 18; ch++) {
        const int p = ch & 1;
        float* Ab = Abuf[p];
        float* Bb = Bbuf[p];
        float* An = Abuf[p ^ 1];

        CP_WAIT0();                  // B(ch) landed (issued last iteration)
        __syncthreads();             // A(ch)+B(ch) visible; old buffers free

        const bool more = (ch + 1 < 18);
        if (more) {
            if (((ch + 1) & 1) == 0) {
                COORDS(nextoff);
                if (ch + 1 <= 14)
                    nextoff = *(const float2*)(offp + ((ch+3) >> 1) * 2);
            }
            GATHERPL(ch + 1, 0);
            CPB(ch + 1, p ^ 1); CP_COMMIT();
        }

        MMAS(0, Ab, Bb);
        if (more) { WEIGHTSTS(0, An); GATHERPL(ch + 1, 1); }
        MMAS(1, Ab, Bb);
        if (more) { WEIGHTSTS(1, An); GATHERPL(ch + 1, 2); }
        MMAS(2, Ab, Bb);
        if (more) { WEIGHTSTS(2, An); GATHERPL(ch + 1, 3); }
        MMAS(3, Ab, Bb);
        if (more) { WEIGHTSTS(3, An); }
    }

    // ---- epilogue ----
    #pragma unroll
    for (int sub = 0; sub < 2; sub++)
        #pragma unroll
        for (int mf = 0; mf < 2; mf++) {
            const int row = p0 + sub*64 + m_base + mf*16 + g;
            #pragma unroll
            for (int nf = 0; nf < 4; nf++) {
                const int col = n_base + nf*8 + 2*tc;
                *(float2*)&out[(size_t)row * F_ + col] =
                    make_float2(acc[sub][mf][nf][0], acc[sub][mf][nf][1]);
                *(float2*)&out[(size_t)(row + 8) * F_ + col] =
                    make_float2(acc[sub][mf][nf][2], acc[sub][mf][nf][3]);
            }
        }
}

// ---------------------------------------------------------------------------
extern "C" void kernel_launch(void* const* d_in, const int* in_sizes, int n_in,
                              void* d_out, int out_size)
{
    const float* x     = (const float*)d_in[0];
    const float* w_off = (const float*)d_in[1];
    const float* b_off = (const float*)d_in[2];
    const float* w_out = (const float*)d_in[3];
    const float* b_out = (const float*)d_in[4];
    float* out = (float*)d_out;

    cudaFuncSetAttribute(offset_conv_kernel,
                         cudaFuncAttributeMaxDynamicSharedMemorySize, SM1_TOTAL);
    cudaFuncSetAttribute(dconv_gemm_mma,
                         cudaFuncAttributeMaxDynamicSharedMemorySize, SM2_TOTAL);

    prep_wp_kernel    <<<(18*BBUF + 255)/256, 256>>>(w_out);
    prep_woff2_kernel <<<(5760 + 255)/256, 256>>>(w_off);
    transpose_x       <<<B_ * H_, 256>>>((const float4*)x);
    offset_conv_kernel<<<B_ * H_, 256, SM1_TOTAL>>>(x, b_off);
    dconv_gemm_mma    <<<(B_*H_*W_)/128, 256, SM2_TOTAL>>>(b_out, out);
}

// round 14
// speedup vs baseline: 1.3270x; 1.0796x over previous
#include <cuda_runtime.h>
#include <cstdint>

#define B_  8
#define H_  128
#define W_  128
#define C_  64
#define F_  128

#define SB   136  // B smem stride: banks (tc*8+g) -> conflict-free frags
#define SA3  136  // A smem stride (128 px + 8 pad)
#define BBUF (32*SB)                        // 4352 floats
#define ABUF2 (32*SA3)                      // 4352 floats

// scratch
__device__ float  g_offsets[B_*H_*W_*18];   // predicted offsets [B,H,W,18]
__device__ float  g_wTp[18*BBUF];           // w_out tf32, pre-padded [ch][kk*SB+n]
__device__ float2 g_wOff2[3*3*64*10];       // w_off as oc-pairs [dydx][c][10]
__device__ float4 g_xT[B_*16*H_*W_];        // x channel-blocked [b][c/4][y][x]

__device__ __forceinline__ uint32_t f2tf32(float f){
    uint32_t r; asm("cvt.rna.tf32.f32 %0, %1;" : "=r"(r) : "f"(f)); return r;
}
__device__ __forceinline__ unsigned long long pack2(float x, float y){
    unsigned long long r;
    asm("mov.b64 %0, {%1,%2};" : "=l"(r) : "f"(x), "f"(y));
    return r;
}
__device__ __forceinline__ void ffma2(unsigned long long& acc,
                                      unsigned long long a, unsigned long long w){
    asm("fma.rn.f32x2 %0, %1, %2, %0;" : "+l"(acc) : "l"(a), "l"(w));
}
__device__ __forceinline__ void addf2(unsigned long long& acc, unsigned long long v){
    asm("add.rn.f32x2 %0, %1, %2;" : "=l"(acc) : "l"(acc), "l"(v));
}
__device__ __forceinline__ uint32_t smem_u32(const void* p){
    uint32_t a;
    asm("{ .reg .u64 t; cvta.to.shared.u64 t, %1; cvt.u32.u64 %0, t; }":"=r"(a):"l"(p));
    return a;
}
__device__ __forceinline__ void cpasync16(uint32_t dst, const void* src){
    asm volatile("cp.async.cg.shared.global [%0], [%1], 16;"::"r"(dst),"l"(src):"memory");
}
#define CP_COMMIT() asm volatile("cp.async.commit_group;":::"memory")
#define CP_WAIT0()  asm volatile("cp.async.wait_group 0;":::"memory")

__device__ __forceinline__ void mma_tf32(float* d, const uint32_t* a, const uint32_t* bb){
    asm volatile(
      "mma.sync.aligned.m16n8k8.row.col.f32.tf32.tf32.f32 "
      "{%0,%1,%2,%3}, {%4,%5,%6,%7}, {%8,%9}, {%0,%1,%2,%3};"
      : "+f"(d[0]),"+f"(d[1]),"+f"(d[2]),"+f"(d[3])
      : "r"(a[0]),"r"(a[1]),"r"(a[2]),"r"(a[3]),"r"(bb[0]),"r"(bb[1]));
}

// ---------------------------------------------------------------------------
// Prep kernels (unchanged)
// ---------------------------------------------------------------------------
__global__ void prep_wp_kernel(const float* __restrict__ w_out)
{
    int idx = blockIdx.x * 256 + threadIdx.x;   // 18*BBUF = 78336
    if (idx >= 18*BBUF) return;
    int n  = idx % SB;
    int kk = (idx / SB) & 31;
    int ch = idx / BBUF;
    float v = 0.f;
    if (n < 128) v = __uint_as_float(f2tf32(w_out[(ch*32 + kk)*128 + n]));
    g_wTp[idx] = v;
}
__global__ void prep_woff2_kernel(const float* __restrict__ w_off)
{
    int idx = blockIdx.x * 256 + threadIdx.x;   // 5760
    if (idx >= 5760) return;
    int p    = idx % 10;
    int c    = (idx / 10) % 64;
    int dydx = idx / 640;
    float2 v = make_float2(0.f, 0.f);
    if (p < 9) {
        v.x = w_off[(dydx*64 + c)*18 + 2*p];
        v.y = w_off[(dydx*64 + c)*18 + 2*p + 1];
    }
    g_wOff2[idx] = v;
}
__global__ __launch_bounds__(256) void transpose_x(const float4* __restrict__ x4)
{
    const int blk  = blockIdx.x;
    const int px   = threadIdx.x & 127;
    const int half = threadIdx.x >> 7;
    const int b = blk >> 7, y = blk & 127;
    const int pix16 = (blk * 128 + px) * 16;
    #pragma unroll
    for (int q = 0; q < 8; q++) {
        int cb = half * 8 + q;
        g_xT[((b*16 + cb) << 14) + y*128 + px] = x4[pix16 + cb];
    }
}

// ---------------------------------------------------------------------------
// Kernel 1: 3x3 SAME conv 64->18, fp32 f32x2.
// 2 pixels per thread (s, s+64), channel-quarter split (q = 16 channels):
// each weight load feeds 2 ffma2. Same row buffer / smem as round-11 (49.7KB).
// ---------------------------------------------------------------------------
#define ROWF   (130*66)
#define WSLICE (3*64*10)
#define SM1_TOTAL ((ROWF + WSLICE*2) * 4)       // 49680 B

__global__ __launch_bounds__(256) void offset_conv_kernel(
    const float* __restrict__ x, const float* __restrict__ b_off)
{
    extern __shared__ float sm1[];
    float* row = sm1;                                        // [130][66]
    unsigned long long* wsh = (unsigned long long*)(sm1 + ROWF);

    const int t   = threadIdx.x;
    const int pms = t & 127;               // staging pixel
    const int sth = t >> 7;                // staging channel half
    const int s   = t & 63;                // compute pixel slot: px0=s, px1=s+64
    const int q   = t >> 6;                // channel quarter (16 ch)
    const int by  = blockIdx.x;
    const int b   = by >> 7;
    const int y   = by & 127;

    unsigned long long acc[2][9];
    #pragma unroll
    for (int p = 0; p < 9; p++) {
        unsigned long long bz = (q == 0) ? pack2(b_off[2*p], b_off[2*p+1])
                                         : pack2(0.f, 0.f);
        acc[0][p] = bz;  acc[1][p] = bz;
    }

    for (int dy = 0; dy < 3; dy++) {
        __syncthreads();                   // protect previous iter's reads
        const int yy = y + dy - 1;
        {   // stage this dy's weight slice
            const unsigned long long* src =
                (const unsigned long long*)g_wOff2 + dy * WSLICE;
            for (int i = t; i < WSLICE; i += 256) wsh[i] = src[i];
        }
        if (t < 2) {                       // zero pads
            const int e = (t == 0) ? 0 : 129;
            float2* z = (float2*)&row[e * 66];
            #pragma unroll
            for (int i = 0; i < 32; i++) z[i] = make_float2(0.f, 0.f);
        }
        {   // stage input row (pms / sth mapping, independent of compute map)
            float2* dst = (float2*)&row[(pms + 1) * 66] + sth * 16;
            if (yy >= 0 && yy < 128) {
                const float4* src =
                    (const float4*)&x[((b * H_ + yy) * W_ + pms) * C_ + sth * 32];
                #pragma unroll
                for (int i = 0; i < 8; i++) {
                    float4 v = src[i];
                    dst[2*i]   = make_float2(v.x, v.y);
                    dst[2*i+1] = make_float2(v.z, v.w);
                }
            } else {
                #pragma unroll
                for (int i = 0; i < 16; i++) dst[i] = make_float2(0.f, 0.f);
            }
        }
        __syncthreads();

        #pragma unroll
        for (int dx = 0; dx < 3; dx++) {
            const float* r0 = &row[(s      + dx) * 66 + q * 16];
            const float* r1 = &row[(s + 64 + dx) * 66 + q * 16];
            const unsigned long long* wq = wsh + dx * 640 + q * 160;
            #pragma unroll 4
            for (int c = 0; c < 16; c += 2) {
                const float2 v0 = *(const float2*)&r0[c];
                const float2 v1 = *(const float2*)&r1[c];
                const unsigned long long* wx = wq + c * 10;
                const unsigned long long* wy = wx + 10;
                const unsigned long long ax0 = pack2(v0.x, v0.x);
                const unsigned long long ax1 = pack2(v1.x, v1.x);
                #pragma unroll
                for (int p = 0; p < 9; p++) {
                    const unsigned long long w = wx[p];
                    ffma2(acc[0][p], ax0, w);
                    ffma2(acc[1][p], ax1, w);
                }
                const unsigned long long ay0 = pack2(v0.y, v0.y);
                const unsigned long long ay1 = pack2(v1.y, v1.y);
                #pragma unroll
                for (int p = 0; p < 9; p++) {
                    const unsigned long long w = wy[p];
                    ffma2(acc[0][p], ay0, w);
                    ffma2(acc[1][p], ay1, w);
                }
            }
        }
    }

    // cross-quarter reduction (reuse row area: 3*128*9 u64 = 27648 B < 34320)
    __syncthreads();
    unsigned long long* red = (unsigned long long*)sm1;
    if (q > 0) {
        #pragma unroll
        for (int r = 0; r < 2; r++) {
            const int px = s + r * 64;
            #pragma unroll
            for (int p = 0; p < 9; p++)
                red[((q - 1) * 128 + px) * 9 + p] = acc[r][p];
        }
    }
    __syncthreads();
    if (q == 0) {
        #pragma unroll
        for (int r = 0; r < 2; r++) {
            const int px = s + r * 64;
            float2* op = (float2*)&g_offsets[((b * H_ + y) * W_ + px) * 18];
            #pragma unroll
            for (int p = 0; p < 9; p++) {
                addf2(acc[r][p], red[(0 * 128 + px) * 9 + p]);
                addf2(acc[r][p], red[(1 * 128 + px) * 9 + p]);
                addf2(acc[r][p], red[(2 * 128 + px) * 9 + p]);
                float lo, hi;
                asm("mov.b64 {%0,%1}, %2;" : "=f"(lo), "=f"(hi) : "l"(acc[r][p]));
                op[p] = make_float2(lo, hi);
            }
        }
    }
}

// ---------------------------------------------------------------------------
// Kernel 2: fused sampling + tf32 mma GEMM (round-13 winner, unchanged)
// ---------------------------------------------------------------------------
#define SM2_TOTAL ((2*ABUF2 + 2*BBUF)*4)    // 69632 B -> 2 blocks/SM

__global__ __launch_bounds__(256, 2) void dconv_gemm_mma(
    const float* __restrict__ b_out, float* __restrict__ out)
{
    extern __shared__ float sm[];
    float* Abuf[2] = { sm, sm + ABUF2 };
    float* Bbuf[2] = { sm + 2*ABUF2, sm + 2*ABUF2 + BBUF };
    const uint32_t Bu = smem_u32(sm + 2*ABUF2);

    const int tid  = threadIdx.x;
    const int wid  = tid >> 5;
    const int lane = tid & 31;
    const int g  = lane >> 2;
    const int tc = lane & 3;

    const int p0 = blockIdx.x * 128;
    const int b  = p0 >> 14;
    const int y  = (p0 >> 7) & 127;
    const int pm = tid & 127;
    const int h  = tid >> 7;

    const int m_base = (wid >> 2) * 32;
    const int n_base = (wid & 3) * 32;
    const float* offp = &g_offsets[(p0 + pm) * 18];

    float acc[2][2][4][4];
    #pragma unroll
    for (int nf = 0; nf < 4; nf++) {
        const int c0 = n_base + nf*8 + 2*tc;
        const float bz0 = __ldg(&b_out[c0]), bz1 = __ldg(&b_out[c0+1]);
        #pragma unroll
        for (int sub = 0; sub < 2; sub++)
            #pragma unroll
            for (int mf = 0; mf < 2; mf++) {
                acc[sub][mf][nf][0] = bz0; acc[sub][mf][nf][1] = bz1;
                acc[sub][mf][nf][2] = bz0; acc[sub][mf][nf][3] = bz1;
            }
    }

    float wa=0.f, wbv=0.f, wcv=0.f, wdv=0.f;
    int i00=0, i10=0, i01=0, i11=0;

    #define COORDS(off) { \
        float nx = fminf(fmaxf((float)pm + (off).x, 0.f), 127.f); \
        float ny = fminf(fmaxf((float)y  + (off).y, 0.f), 127.f); \
        float x0f = floorf(nx), y0f = floorf(ny); \
        float x1f = fminf(x0f + 1.f, 127.f), y1f = fminf(y0f + 1.f, 127.f); \
        float lx = nx - x0f, hx = x1f - nx; \
        float ly = ny - y0f, hy = y1f - ny; \
        wa = hx*hy; wbv = hx*ly; wcv = lx*hy; wdv = lx*ly; \
        int ix0 = (int)x0f, ix1 = (int)x1f, iy0 = (int)y0f, iy1 = (int)y1f; \
        i00 = iy0*128 + ix0;  i10 = iy1*128 + ix0; \
        i01 = iy0*128 + ix1;  i11 = iy1*128 + ix1; }

    float4 ca, cb2, cc2, cd;

    #define GATHERPL(chv, j) { \
        const int cbp = (b*16 + ((chv)&1)*8 + h*4 + (j)) << 14; \
        ca  = g_xT[cbp + i00]; cb2 = g_xT[cbp + i10]; \
        cc2 = g_xT[cbp + i01]; cd  = g_xT[cbp + i11]; }

    #define WEIGHTSTS(j, Ab) { \
        const int kb = h*16 + (j)*4; \
        (Ab)[(kb+0)*SA3 + pm] = __uint_as_float(f2tf32(wa*ca.x + wbv*cb2.x + wcv*cc2.x + wdv*cd.x)); \
        (Ab)[(kb+1)*SA3 + pm] = __uint_as_float(f2tf32(wa*ca.y + wbv*cb2.y + wcv*cc2.y + wdv*cd.y)); \
        (Ab)[(kb+2)*SA3 + pm] = __uint_as_float(f2tf32(wa*ca.z + wbv*cb2.z + wcv*cc2.z + wdv*cd.z)); \
        (Ab)[(kb+3)*SA3 + pm] = __uint_as_float(f2tf32(wa*ca.w + wbv*cb2.w + wcv*cc2.w + wdv*cd.w)); }

    #define CPB(chv, pbuf) { \
        const uint32_t dbase = Bu + (uint32_t)(pbuf) * (BBUF*4u); \
        const char* srcb = (const char*)&g_wTp[(chv) * BBUF]; \
        _Pragma("unroll") \
        for (int i = 0; i < 5; i++) { \
            int idx = tid + i*256; \
            if (idx < 1088) cpasync16(dbase + (uint32_t)idx*16u, srcb + idx*16); \
        } }

    #define MMAS(s, Ab, Bb) { \
        const int k0 = (s) * 8; \
        const uint32_t* Br0 = (const uint32_t*)&(Bb)[(k0 + tc)     * SB]; \
        const uint32_t* Br1 = (const uint32_t*)&(Bb)[(k0 + tc + 4) * SB]; \
        uint32_t bfr[4][2]; \
        _Pragma("unroll") \
        for (int nf = 0; nf < 4; nf++) { \
            const int n = n_base + nf*8 + g; \
            bfr[nf][0] = Br0[n];  bfr[nf][1] = Br1[n]; \
        } \
        const uint32_t* Ar0 = (const uint32_t*)&(Ab)[(k0 + tc)     * SA3]; \
        const uint32_t* Ar1 = (const uint32_t*)&(Ab)[(k0 + tc + 4) * SA3]; \
        _Pragma("unroll") \
        for (int sub = 0; sub < 2; sub++) { \
            uint32_t afr[2][4]; \
            _Pragma("unroll") \
            for (int mf = 0; mf < 2; mf++) { \
                const int m = sub*64 + m_base + mf*16 + g; \
                afr[mf][0] = Ar0[m];  afr[mf][1] = Ar0[m+8]; \
                afr[mf][2] = Ar1[m];  afr[mf][3] = Ar1[m+8]; \
            } \
            _Pragma("unroll") \
            for (int mf = 0; mf < 2; mf++) \
                _Pragma("unroll") \
                for (int nf = 0; nf < 4; nf++) \
                    mma_tf32(acc[sub][mf][nf], afr[mf], bfr[nf]); \
        } }

    float2 curoff  = *(const float2*)(offp + 0);
    float2 nextoff = *(const float2*)(offp + 2);
    COORDS(curoff);
    #pragma unroll
    for (int j = 0; j < 4; j++) {
        GATHERPL(0, j);
        WEIGHTSTS(j, Abuf[0]);
    }
    CPB(0, 0); CP_COMMIT();

    for (int ch = 0; ch < 18; ch++) {
        const int p = ch & 1;
        float* Ab = Abuf[p];
        float* Bb = Bbuf[p];
        float* An = Abuf[p ^ 1];

        CP_WAIT0();
        __syncthreads();

        const bool more = (ch + 1 < 18);
        if (more) {
            if (((ch + 1) & 1) == 0) {
                COORDS(nextoff);
                if (ch + 1 <= 14)
                    nextoff = *(const float2*)(offp + ((ch+3) >> 1) * 2);
            }
            GATHERPL(ch + 1, 0);
            CPB(ch + 1, p ^ 1); CP_COMMIT();
        }

        MMAS(0, Ab, Bb);
        if (more) { WEIGHTSTS(0, An); GATHERPL(ch + 1, 1); }
        MMAS(1, Ab, Bb);
        if (more) { WEIGHTSTS(1, An); GATHERPL(ch + 1, 2); }
        MMAS(2, Ab, Bb);
        if (more) { WEIGHTSTS(2, An); GATHERPL(ch + 1, 3); }
        MMAS(3, Ab, Bb);
        if (more) { WEIGHTSTS(3, An); }
    }

    #pragma unroll
    for (int sub = 0; sub < 2; sub++)
        #pragma unroll
        for (int mf = 0; mf < 2; mf++) {
            const int row = p0 + sub*64 + m_base + mf*16 + g;
            #pragma unroll
            for (int nf = 0; nf < 4; nf++) {
                const int col = n_base + nf*8 + 2*tc;
                *(float2*)&out[(size_t)row * F_ + col] =
                    make_float2(acc[sub][mf][nf][0], acc[sub][mf][nf][1]);
                *(float2*)&out[(size_t)(row + 8) * F_ + col] =
                    make_float2(acc[sub][mf][nf][2], acc[sub][mf][nf][3]);
            }
        }
}

// ---------------------------------------------------------------------------
extern "C" void kernel_launch(void* const* d_in, const int* in_sizes, int n_in,
                              void* d_out, int out_size)
{
    const float* x     = (const float*)d_in[0];
    const float* w_off = (const float*)d_in[1];
    const float* b_off = (const float*)d_in[2];
    const float* w_out = (const float*)d_in[3];
    const float* b_out = (const float*)d_in[4];
    float* out = (float*)d_out;

    cudaFuncSetAttribute(offset_conv_kernel,
                         cudaFuncAttributeMaxDynamicSharedMemorySize, SM1_TOTAL);
    cudaFuncSetAttribute(dconv_gemm_mma,
                         cudaFuncAttributeMaxDynamicSharedMemorySize, SM2_TOTAL);

    prep_wp_kernel    <<<(18*BBUF + 255)/256, 256>>>(w_out);
    prep_woff2_kernel <<<(5760 + 255)/256, 256>>>(w_off);
    transpose_x       <<<B_ * H_, 256>>>((const float4*)x);
    offset_conv_kernel<<<B_ * H_, 256, SM1_TOTAL>>>(x, b_off);
    dconv_gemm_mma    <<<(B_*H_*W_)/128, 256, SM2_TOTAL>>>(b_out, out);
}

// round 15
// speedup vs baseline: 1.3503x; 1.0176x over previous
#include <cuda_runtime.h>
#include <cstdint>

#define B_  8
#define H_  128
#define W_  128
#define C_  64
#define F_  128

#define SB   136  // B smem stride: banks (tc*8+g) -> conflict-free frags
#define SA3  136  // A smem stride (128 px + 8 pad)
#define BBUF (32*SB)                        // 4352 floats
#define ABUF2 (32*SA3)                      // 4352 floats

// scratch
__device__ float  g_offsets[B_*H_*W_*18];   // predicted offsets [B,H,W,18]
__device__ float  g_wTp[18*BBUF];           // w_out tf32, pre-padded [ch][kk*SB+n]
__device__ float2 g_wOff2[3*3*64*10];       // w_off as oc-pairs [dydx][c][10]
__device__ float4 g_xT[B_*16*H_*W_];        // x channel-blocked [b][c/4][y][x]

__device__ __forceinline__ uint32_t f2tf32(float f){
    uint32_t r; asm("cvt.rna.tf32.f32 %0, %1;" : "=r"(r) : "f"(f)); return r;
}
__device__ __forceinline__ unsigned long long pack2(float x, float y){
    unsigned long long r;
    asm("mov.b64 %0, {%1,%2};" : "=l"(r) : "f"(x), "f"(y));
    return r;
}
__device__ __forceinline__ void ffma2(unsigned long long& acc,
                                      unsigned long long a, unsigned long long w){
    asm("fma.rn.f32x2 %0, %1, %2, %0;" : "+l"(acc) : "l"(a), "l"(w));
}
__device__ __forceinline__ void addf2(unsigned long long& acc, unsigned long long v){
    asm("add.rn.f32x2 %0, %1, %2;" : "=l"(acc) : "l"(acc), "l"(v));
}
__device__ __forceinline__ uint32_t smem_u32(const void* p){
    uint32_t a;
    asm("{ .reg .u64 t; cvta.to.shared.u64 t, %1; cvt.u32.u64 %0, t; }":"=r"(a):"l"(p));
    return a;
}
__device__ __forceinline__ void cpasync16(uint32_t dst, const void* src){
    asm volatile("cp.async.cg.shared.global [%0], [%1], 16;"::"r"(dst),"l"(src):"memory");
}
#define CP_COMMIT() asm volatile("cp.async.commit_group;":::"memory")
#define CP_WAIT0()  asm volatile("cp.async.wait_group 0;":::"memory")

__device__ __forceinline__ void mma_tf32(float* d, const uint32_t* a, const uint32_t* bb){
    asm volatile(
      "mma.sync.aligned.m16n8k8.row.col.f32.tf32.tf32.f32 "
      "{%0,%1,%2,%3}, {%4,%5,%6,%7}, {%8,%9}, {%0,%1,%2,%3};"
      : "+f"(d[0]),"+f"(d[1]),"+f"(d[2]),"+f"(d[3])
      : "r"(a[0]),"r"(a[1]),"r"(a[2]),"r"(a[3]),"r"(bb[0]),"r"(bb[1]));
}

// ---------------------------------------------------------------------------
// Fused prep kernel: blockIdx-partitioned (transpose_x | prep_wp | prep_woff2)
// ---------------------------------------------------------------------------
__global__ __launch_bounds__(256) void prep_fused(
    const float* __restrict__ w_out, const float* __restrict__ w_off,
    const float4* __restrict__ x4)
{
    const int blk = blockIdx.x;
    const int tid = threadIdx.x;
    if (blk < 1024) {                       // transpose x
        const int px   = tid & 127;
        const int half = tid >> 7;
        const int b = blk >> 7, y = blk & 127;
        const int pix16 = (blk * 128 + px) * 16;
        #pragma unroll
        for (int qq = 0; qq < 8; qq++) {
            int cb = half * 8 + qq;
            g_xT[((b*16 + cb) << 14) + y*128 + px] = x4[pix16 + cb];
        }
    } else if (blk < 1024 + 306) {          // w_out -> padded tf32
        int idx = (blk - 1024) * 256 + tid; // exactly 18*BBUF = 78336
        int n  = idx % SB;
        int kk = (idx / SB) & 31;
        int ch = idx / BBUF;
        float v = 0.f;
        if (n < 128) v = __uint_as_float(f2tf32(w_out[(ch*32 + kk)*128 + n]));
        g_wTp[idx] = v;
    } else {                                // w_off -> oc-pairs
        int idx = (blk - 1330) * 256 + tid;
        if (idx < 5760) {
            int p    = idx % 10;
            int c    = (idx / 10) % 64;
            int dydx = idx / 640;
            float2 v = make_float2(0.f, 0.f);
            if (p < 9) {
                v.x = w_off[(dydx*64 + c)*18 + 2*p];
                v.y = w_off[(dydx*64 + c)*18 + 2*p + 1];
            }
            g_wOff2[idx] = v;
        }
    }
}

// ---------------------------------------------------------------------------
// Kernel 1: 3x3 SAME conv 64->18, fp32 f32x2, 4 pixels/thread.
// Thread (s, q): pixels s,s+32,s+64,s+96, channel-eighth q (8 ch = warp id).
// Each weight load feeds 4 ffma2. 3-round cross-warp smem reduction.
// ---------------------------------------------------------------------------
#define ROWF   (130*66)
#define WSLICE (3*64*10)
#define SM1_TOTAL ((ROWF + WSLICE*2) * 4)       // 49680 B

__global__ __launch_bounds__(256) void offset_conv_kernel(
    const float* __restrict__ x, const float* __restrict__ b_off)
{
    extern __shared__ float sm1[];
    float* row = sm1;                                        // [130][66]
    unsigned long long* wsh = (unsigned long long*)(sm1 + ROWF);

    const int t   = threadIdx.x;
    const int pms = t & 127;               // staging pixel
    const int sth = t >> 7;                // staging channel half
    const int s   = t & 31;                // compute pixel slot
    const int q   = t >> 5;                // channel eighth (= warp id)
    const int by  = blockIdx.x;
    const int b   = by >> 7;
    const int y   = by & 127;

    unsigned long long acc[4][9];
    #pragma unroll
    for (int p = 0; p < 9; p++) {
        unsigned long long bz = (q == 0) ? pack2(b_off[2*p], b_off[2*p+1])
                                         : pack2(0.f, 0.f);
        #pragma unroll
        for (int r = 0; r < 4; r++) acc[r][p] = bz;
    }

    for (int dy = 0; dy < 3; dy++) {
        __syncthreads();                   // protect previous iter's reads
        const int yy = y + dy - 1;
        {   // stage this dy's weight slice
            const unsigned long long* src =
                (const unsigned long long*)g_wOff2 + dy * WSLICE;
            for (int i = t; i < WSLICE; i += 256) wsh[i] = src[i];
        }
        if (t < 2) {                       // zero pads
            const int e = (t == 0) ? 0 : 129;
            float2* z = (float2*)&row[e * 66];
            #pragma unroll
            for (int i = 0; i < 32; i++) z[i] = make_float2(0.f, 0.f);
        }
        {   // stage input row
            float2* dst = (float2*)&row[(pms + 1) * 66] + sth * 16;
            if (yy >= 0 && yy < 128) {
                const float4* src =
                    (const float4*)&x[((b * H_ + yy) * W_ + pms) * C_ + sth * 32];
                #pragma unroll
                for (int i = 0; i < 8; i++) {
                    float4 v = src[i];
                    dst[2*i]   = make_float2(v.x, v.y);
                    dst[2*i+1] = make_float2(v.z, v.w);
                }
            } else {
                #pragma unroll
                for (int i = 0; i < 16; i++) dst[i] = make_float2(0.f, 0.f);
            }
        }
        __syncthreads();

        #pragma unroll
        for (int dx = 0; dx < 3; dx++) {
            const float* r0 = &row[(s      + dx) * 66 + q * 8];
            const float* r1 = &row[(s + 32 + dx) * 66 + q * 8];
            const float* r2 = &row[(s + 64 + dx) * 66 + q * 8];
            const float* r3 = &row[(s + 96 + dx) * 66 + q * 8];
            const unsigned long long* wq = wsh + dx * 640 + q * 80;
            #pragma unroll
            for (int c = 0; c < 8; c += 2) {
                const float2 v0 = *(const float2*)&r0[c];
                const float2 v1 = *(const float2*)&r1[c];
                const float2 v2 = *(const float2*)&r2[c];
                const float2 v3 = *(const float2*)&r3[c];
                const unsigned long long* wx = wq + c * 10;
                const unsigned long long* wy = wx + 10;
                {
                    const unsigned long long a0 = pack2(v0.x, v0.x);
                    const unsigned long long a1 = pack2(v1.x, v1.x);
                    const unsigned long long a2 = pack2(v2.x, v2.x);
                    const unsigned long long a3 = pack2(v3.x, v3.x);
                    #pragma unroll
                    for (int p = 0; p < 9; p++) {
                        const unsigned long long w = wx[p];
                        ffma2(acc[0][p], a0, w);
                        ffma2(acc[1][p], a1, w);
                        ffma2(acc[2][p], a2, w);
                        ffma2(acc[3][p], a3, w);
                    }
                }
                {
                    const unsigned long long a0 = pack2(v0.y, v0.y);
                    const unsigned long long a1 = pack2(v1.y, v1.y);
                    const unsigned long long a2 = pack2(v2.y, v2.y);
                    const unsigned long long a3 = pack2(v3.y, v3.y);
                    #pragma unroll
                    for (int p = 0; p < 9; p++) {
                        const unsigned long long w = wy[p];
                        ffma2(acc[0][p], a0, w);
                        ffma2(acc[1][p], a1, w);
                        ffma2(acc[2][p], a2, w);
                        ffma2(acc[3][p], a3, w);
                    }
                }
            }
        }
    }

    // 3-round cross-warp reduction (red stride 9 u64 -> conflict-free)
    __syncthreads();
    unsigned long long* red = (unsigned long long*)sm1;  // <= 4*128*9 u64 = 36864B

    if (q >= 4) {
        #pragma unroll
        for (int r = 0; r < 4; r++)
            #pragma unroll
            for (int p = 0; p < 9; p++)
                red[((q - 4) * 128 + s + r*32) * 9 + p] = acc[r][p];
    }
    __syncthreads();
    if (q < 4) {
        #pragma unroll
        for (int r = 0; r < 4; r++)
            #pragma unroll
            for (int p = 0; p < 9; p++)
                addf2(acc[r][p], red[(q * 128 + s + r*32) * 9 + p]);
    }
    __syncthreads();
    if (q == 2 || q == 3) {
        #pragma unroll
        for (int r = 0; r < 4; r++)
            #pragma unroll
            for (int p = 0; p < 9; p++)
                red[((q - 2) * 128 + s + r*32) * 9 + p] = acc[r][p];
    }
    __syncthreads();
    if (q < 2) {
        #pragma unroll
        for (int r = 0; r < 4; r++)
            #pragma unroll
            for (int p = 0; p < 9; p++)
                addf2(acc[r][p], red[(q * 128 + s + r*32) * 9 + p]);
    }
    __syncthreads();
    if (q == 1) {
        #pragma unroll
        for (int r = 0; r < 4; r++)
            #pragma unroll
            for (int p = 0; p < 9; p++)
                red[(s + r*32) * 9 + p] = acc[r][p];
    }
    __syncthreads();
    if (q == 0) {
        #pragma unroll
        for (int r = 0; r < 4; r++) {
            const int px = s + r*32;
            float2* op = (float2*)&g_offsets[((b * H_ + y) * W_ + px) * 18];
            #pragma unroll
            for (int p = 0; p < 9; p++) {
                addf2(acc[r][p], red[px * 9 + p]);
                float lo, hi;
                asm("mov.b64 {%0,%1}, %2;" : "=f"(lo), "=f"(hi) : "l"(acc[r][p]));
                op[p] = make_float2(lo, hi);
            }
        }
    }
}

// ---------------------------------------------------------------------------
// Kernel 2: fused sampling + tf32 mma GEMM (round-13 winner, unchanged)
// ---------------------------------------------------------------------------
#define SM2_TOTAL ((2*ABUF2 + 2*BBUF)*4)    // 69632 B -> 2 blocks/SM

__global__ __launch_bounds__(256, 2) void dconv_gemm_mma(
    const float* __restrict__ b_out, float* __restrict__ out)
{
    extern __shared__ float sm[];
    float* Abuf[2] = { sm, sm + ABUF2 };
    float* Bbuf[2] = { sm + 2*ABUF2, sm + 2*ABUF2 + BBUF };
    const uint32_t Bu = smem_u32(sm + 2*ABUF2);

    const int tid  = threadIdx.x;
    const int wid  = tid >> 5;
    const int lane = tid & 31;
    const int g  = lane >> 2;
    const int tc = lane & 3;

    const int p0 = blockIdx.x * 128;
    const int b  = p0 >> 14;
    const int y  = (p0 >> 7) & 127;
    const int pm = tid & 127;
    const int h  = tid >> 7;

    const int m_base = (wid >> 2) * 32;
    const int n_base = (wid & 3) * 32;
    const float* offp = &g_offsets[(p0 + pm) * 18];

    float acc[2][2][4][4];
    #pragma unroll
    for (int nf = 0; nf < 4; nf++) {
        const int c0 = n_base + nf*8 + 2*tc;
        const float bz0 = __ldg(&b_out[c0]), bz1 = __ldg(&b_out[c0+1]);
        #pragma unroll
        for (int sub = 0; sub < 2; sub++)
            #pragma unroll
            for (int mf = 0; mf < 2; mf++) {
                acc[sub][mf][nf][0] = bz0; acc[sub][mf][nf][1] = bz1;
                acc[sub][mf][nf][2] = bz0; acc[sub][mf][nf][3] = bz1;
            }
    }

    float wa=0.f, wbv=0.f, wcv=0.f, wdv=0.f;
    int i00=0, i10=0, i01=0, i11=0;

    #define COORDS(off) { \
        float nx = fminf(fmaxf((float)pm + (off).x, 0.f), 127.f); \
        float ny = fminf(fmaxf((float)y  + (off).y, 0.f), 127.f); \
        float x0f = floorf(nx), y0f = floorf(ny); \
        float x1f = fminf(x0f + 1.f, 127.f), y1f = fminf(y0f + 1.f, 127.f); \
        float lx = nx - x0f, hx = x1f - nx; \
        float ly = ny - y0f, hy = y1f - ny; \
        wa = hx*hy; wbv = hx*ly; wcv = lx*hy; wdv = lx*ly; \
        int ix0 = (int)x0f, ix1 = (int)x1f, iy0 = (int)y0f, iy1 = (int)y1f; \
        i00 = iy0*128 + ix0;  i10 = iy1*128 + ix0; \
        i01 = iy0*128 + ix1;  i11 = iy1*128 + ix1; }

    float4 ca, cb2, cc2, cd;

    #define GATHERPL(chv, j) { \
        const int cbp = (b*16 + ((chv)&1)*8 + h*4 + (j)) << 14; \
        ca  = g_xT[cbp + i00]; cb2 = g_xT[cbp + i10]; \
        cc2 = g_xT[cbp + i01]; cd  = g_xT[cbp + i11]; }

    #define WEIGHTSTS(j, Ab) { \
        const int kb = h*16 + (j)*4; \
        (Ab)[(kb+0)*SA3 + pm] = __uint_as_float(f2tf32(wa*ca.x + wbv*cb2.x + wcv*cc2.x + wdv*cd.x)); \
        (Ab)[(kb+1)*SA3 + pm] = __uint_as_float(f2tf32(wa*ca.y + wbv*cb2.y + wcv*cc2.y + wdv*cd.y)); \
        (Ab)[(kb+2)*SA3 + pm] = __uint_as_float(f2tf32(wa*ca.z + wbv*cb2.z + wcv*cc2.z + wdv*cd.z)); \
        (Ab)[(kb+3)*SA3 + pm] = __uint_as_float(f2tf32(wa*ca.w + wbv*cb2.w + wcv*cc2.w + wdv*cd.w)); }

    #define CPB(chv, pbuf) { \
        const uint32_t dbase = Bu + (uint32_t)(pbuf) * (BBUF*4u); \
        const char* srcb = (const char*)&g_wTp[(chv) * BBUF]; \
        _Pragma("unroll") \
        for (int i = 0; i < 5; i++) { \
            int idx = tid + i*256; \
            if (idx < 1088) cpasync16(dbase + (uint32_t)idx*16u, srcb + idx*16); \
        } }

    #define MMAS(s, Ab, Bb) { \
        const int k0 = (s) * 8; \
        const uint32_t* Br0 = (const uint32_t*)&(Bb)[(k0 + tc)     * SB]; \
        const uint32_t* Br1 = (const uint32_t*)&(Bb)[(k0 + tc + 4) * SB]; \
        uint32_t bfr[4][2]; \
        _Pragma("unroll") \
        for (int nf = 0; nf < 4; nf++) { \
            const int n = n_base + nf*8 + g; \
            bfr[nf][0] = Br0[n];  bfr[nf][1] = Br1[n]; \
        } \
        const uint32_t* Ar0 = (const uint32_t*)&(Ab)[(k0 + tc)     * SA3]; \
        const uint32_t* Ar1 = (const uint32_t*)&(Ab)[(k0 + tc + 4) * SA3]; \
        _Pragma("unroll") \
        for (int sub = 0; sub < 2; sub++) { \
            uint32_t afr[2][4]; \
            _Pragma("unroll") \
            for (int mf = 0; mf < 2; mf++) { \
                const int m = sub*64 + m_base + mf*16 + g; \
                afr[mf][0] = Ar0[m];  afr[mf][1] = Ar0[m+8]; \
                afr[mf][2] = Ar1[m];  afr[mf][3] = Ar1[m+8]; \
            } \
            _Pragma("unroll") \
            for (int mf = 0; mf < 2; mf++) \
                _Pragma("unroll") \
                for (int nf = 0; nf < 4; nf++) \
                    mma_tf32(acc[sub][mf][nf], afr[mf], bfr[nf]); \
        } }

    float2 curoff  = *(const float2*)(offp + 0);
    float2 nextoff = *(const float2*)(offp + 2);
    COORDS(curoff);
    #pragma unroll
    for (int j = 0; j < 4; j++) {
        GATHERPL(0, j);
        WEIGHTSTS(j, Abuf[0]);
    }
    CPB(0, 0); CP_COMMIT();

    for (int ch = 0; ch < 18; ch++) {
        const int p = ch & 1;
        float* Ab = Abuf[p];
        float* Bb = Bbuf[p];
        float* An = Abuf[p ^ 1];

        CP_WAIT0();
        __syncthreads();

        const bool more = (ch + 1 < 18);
        if (more) {
            if (((ch + 1) & 1) == 0) {
                COORDS(nextoff);
                if (ch + 1 <= 14)
                    nextoff = *(const float2*)(offp + ((ch+3) >> 1) * 2);
            }
            GATHERPL(ch + 1, 0);
            CPB(ch + 1, p ^ 1); CP_COMMIT();
        }

        MMAS(0, Ab, Bb);
        if (more) { WEIGHTSTS(0, An); GATHERPL(ch + 1, 1); }
        MMAS(1, Ab, Bb);
        if (more) { WEIGHTSTS(1, An); GATHERPL(ch + 1, 2); }
        MMAS(2, Ab, Bb);
        if (more) { WEIGHTSTS(2, An); GATHERPL(ch + 1, 3); }
        MMAS(3, Ab, Bb);
        if (more) { WEIGHTSTS(3, An); }
    }

    #pragma unroll
    for (int sub = 0; sub < 2; sub++)
        #pragma unroll
        for (int mf = 0; mf < 2; mf++) {
            const int row = p0 + sub*64 + m_base + mf*16 + g;
            #pragma unroll
            for (int nf = 0; nf < 4; nf++) {
                const int col = n_base + nf*8 + 2*tc;
                *(float2*)&out[(size_t)row * F_ + col] =
                    make_float2(acc[sub][mf][nf][0], acc[sub][mf][nf][1]);
                *(float2*)&out[(size_t)(row + 8) * F_ + col] =
                    make_float2(acc[sub][mf][nf][2], acc[sub][mf][nf][3]);
            }
        }
}

// ---------------------------------------------------------------------------
extern "C" void kernel_launch(void* const* d_in, const int* in_sizes, int n_in,
                              void* d_out, int out_size)
{
    const float* x     = (const float*)d_in[0];
    const float* w_off = (const float*)d_in[1];
    const float* b_off = (const float*)d_in[2];
    const float* w_out = (const float*)d_in[3];
    const float* b_out = (const float*)d_in[4];
    float* out = (float*)d_out;

    cudaFuncSetAttribute(offset_conv_kernel,
                         cudaFuncAttributeMaxDynamicSharedMemorySize, SM1_TOTAL);
    cudaFuncSetAttribute(dconv_gemm_mma,
                         cudaFuncAttributeMaxDynamicSharedMemorySize, SM2_TOTAL);

    prep_fused        <<<1353, 256>>>(w_out, w_off, (const float4*)x);
    offset_conv_kernel<<<B_ * H_, 256, SM1_TOTAL>>>(x, b_off);
    dconv_gemm_mma    <<<(B_*H_*W_)/128, 256, SM2_TOTAL>>>(b_out, out);
}

// round 16
// speedup vs baseline: 1.4032x; 1.0392x over previous
#include <cuda_runtime.h>
#include <cstdint>

#define B_  8
#define H_  128
#define W_  128
#define C_  64
#define F_  128

#define SB   136  // B smem stride: banks (tc*8+g) -> conflict-free frags
#define SA3  136  // A smem stride (128 px + 8 pad)
#define BBUF (32*SB)                        // 4352 floats
#define ABUF2 (32*SA3)                      // 4352 floats

// scratch
__device__ float  g_offsets[B_*H_*W_*18];   // predicted offsets [B,H,W,18]
__device__ float  g_wTp[18*BBUF];           // w_out tf32, pre-padded [ch][kk*SB+n]
__device__ float2 g_wOff2[3*3*64*10];       // w_off as oc-pairs [dydx][c][10]
__device__ float4 g_xT[B_*16*H_*W_];        // x channel-blocked [b][c/4][y][x]

__device__ __forceinline__ uint32_t f2tf32(float f){
    uint32_t r; asm("cvt.rna.tf32.f32 %0, %1;" : "=r"(r) : "f"(f)); return r;
}
__device__ __forceinline__ unsigned long long pack2(float x, float y){
    unsigned long long r;
    asm("mov.b64 %0, {%1,%2};" : "=l"(r) : "f"(x), "f"(y));
    return r;
}
__device__ __forceinline__ void ffma2(unsigned long long& acc,
                                      unsigned long long a, unsigned long long w){
    asm("fma.rn.f32x2 %0, %1, %2, %0;" : "+l"(acc) : "l"(a), "l"(w));
}
__device__ __forceinline__ void addf2(unsigned long long& acc, unsigned long long v){
    asm("add.rn.f32x2 %0, %1, %2;" : "=l"(acc) : "l"(acc), "l"(v));
}
__device__ __forceinline__ uint32_t smem_u32(const void* p){
    uint32_t a;
    asm("{ .reg .u64 t; cvta.to.shared.u64 t, %1; cvt.u32.u64 %0, t; }":"=r"(a):"l"(p));
    return a;
}
__device__ __forceinline__ void cpasync16(uint32_t dst, const void* src){
    asm volatile("cp.async.cg.shared.global [%0], [%1], 16;"::"r"(dst),"l"(src):"memory");
}
#define CP_COMMIT() asm volatile("cp.async.commit_group;":::"memory")
#define CP_WAIT0()  asm volatile("cp.async.wait_group 0;":::"memory")

__device__ __forceinline__ void mma_tf32(float* d, const uint32_t* a, const uint32_t* bb){
    asm volatile(
      "mma.sync.aligned.m16n8k8.row.col.f32.tf32.tf32.f32 "
      "{%0,%1,%2,%3}, {%4,%5,%6,%7}, {%8,%9}, {%0,%1,%2,%3};"
      : "+f"(d[0]),"+f"(d[1]),"+f"(d[2]),"+f"(d[3])
      : "r"(a[0]),"r"(a[1]),"r"(a[2]),"r"(a[3]),"r"(bb[0]),"r"(bb[1]));
}

// ---------------------------------------------------------------------------
// Fused prep kernel: blockIdx-partitioned (transpose_x | prep_wp | prep_woff2)
// ---------------------------------------------------------------------------
__global__ __launch_bounds__(256) void prep_fused(
    const float* __restrict__ w_out, const float* __restrict__ w_off,
    const float4* __restrict__ x4)
{
    const int blk = blockIdx.x;
    const int tid = threadIdx.x;
    if (blk < 1024) {                       // transpose x
        const int px   = tid & 127;
        const int half = tid >> 7;
        const int b = blk >> 7, y = blk & 127;
        const int pix16 = (blk * 128 + px) * 16;
        #pragma unroll
        for (int qq = 0; qq < 8; qq++) {
            int cb = half * 8 + qq;
            g_xT[((b*16 + cb) << 14) + y*128 + px] = x4[pix16 + cb];
        }
    } else if (blk < 1024 + 306) {          // w_out -> padded tf32
        int idx = (blk - 1024) * 256 + tid; // exactly 18*BBUF = 78336
        int n  = idx % SB;
        int kk = (idx / SB) & 31;
        int ch = idx / BBUF;
        float v = 0.f;
        if (n < 128) v = __uint_as_float(f2tf32(w_out[(ch*32 + kk)*128 + n]));
        g_wTp[idx] = v;
    } else {                                // w_off -> oc-pairs
        int idx = (blk - 1330) * 256 + tid;
        if (idx < 5760) {
            int p    = idx % 10;
            int c    = (idx / 10) % 64;
            int dydx = idx / 640;
            float2 v = make_float2(0.f, 0.f);
            if (p < 9) {
                v.x = w_off[(dydx*64 + c)*18 + 2*p];
                v.y = w_off[(dydx*64 + c)*18 + 2*p + 1];
            }
            g_wOff2[idx] = v;
        }
    }
}

// ---------------------------------------------------------------------------
// FUSED kernel: phase 1 = offset conv (fp32 f32x2, 4 px/thread), phase 2 =
// bilinear sampling + tf32 mma GEMM. Same block = same image row for both.
// Offsets written to gmem in phase 1, read back after __syncthreads (block-
// level global visibility). smem: phase1 49.7KB union'd with phase2 69.6KB.
// ---------------------------------------------------------------------------
#define ROWF   (130*66)
#define WSLICE (3*64*10)
#define SM2_TOTAL ((2*ABUF2 + 2*BBUF)*4)    // 69632 B -> 2 blocks/SM

__global__ __launch_bounds__(256, 2) void dconv_fused(
    const float* __restrict__ x, const float* __restrict__ b_off,
    const float* __restrict__ b_out, float* __restrict__ out)
{
    extern __shared__ float sm[];

    const int tid = threadIdx.x;
    const int by  = blockIdx.x;           // b*128 + y

    // ======================= PHASE 1: offset conv =======================
    {
        float* row = sm;                                         // [130][66]
        unsigned long long* wsh = (unsigned long long*)(sm + ROWF);

        const int pms = tid & 127;
        const int sth = tid >> 7;
        const int s   = tid & 31;
        const int q   = tid >> 5;
        const int b   = by >> 7;
        const int y   = by & 127;

        unsigned long long acc1[4][9];
        #pragma unroll
        for (int p = 0; p < 9; p++) {
            unsigned long long bz = (q == 0) ? pack2(b_off[2*p], b_off[2*p+1])
                                             : pack2(0.f, 0.f);
            #pragma unroll
            for (int r = 0; r < 4; r++) acc1[r][p] = bz;
        }

        for (int dy = 0; dy < 3; dy++) {
            __syncthreads();
            const int yy = y + dy - 1;
            {
                const unsigned long long* src =
                    (const unsigned long long*)g_wOff2 + dy * WSLICE;
                for (int i = tid; i < WSLICE; i += 256) wsh[i] = src[i];
            }
            if (tid < 2) {
                const int e = (tid == 0) ? 0 : 129;
                float2* z = (float2*)&row[e * 66];
                #pragma unroll
                for (int i = 0; i < 32; i++) z[i] = make_float2(0.f, 0.f);
            }
            {
                float2* dst = (float2*)&row[(pms + 1) * 66] + sth * 16;
                if (yy >= 0 && yy < 128) {
                    const float4* src =
                        (const float4*)&x[((b * H_ + yy) * W_ + pms) * C_ + sth * 32];
                    #pragma unroll
                    for (int i = 0; i < 8; i++) {
                        float4 v = src[i];
                        dst[2*i]   = make_float2(v.x, v.y);
                        dst[2*i+1] = make_float2(v.z, v.w);
                    }
                } else {
                    #pragma unroll
                    for (int i = 0; i < 16; i++) dst[i] = make_float2(0.f, 0.f);
                }
            }
            __syncthreads();

            #pragma unroll
            for (int dx = 0; dx < 3; dx++) {
                const float* r0 = &row[(s      + dx) * 66 + q * 8];
                const float* r1 = &row[(s + 32 + dx) * 66 + q * 8];
                const float* r2 = &row[(s + 64 + dx) * 66 + q * 8];
                const float* r3 = &row[(s + 96 + dx) * 66 + q * 8];
                const unsigned long long* wq = wsh + dx * 640 + q * 80;
                #pragma unroll
                for (int c = 0; c < 8; c += 2) {
                    const float2 v0 = *(const float2*)&r0[c];
                    const float2 v1 = *(const float2*)&r1[c];
                    const float2 v2 = *(const float2*)&r2[c];
                    const float2 v3 = *(const float2*)&r3[c];
                    const unsigned long long* wx = wq + c * 10;
                    const unsigned long long* wy = wx + 10;
                    {
                        const unsigned long long a0 = pack2(v0.x, v0.x);
                        const unsigned long long a1 = pack2(v1.x, v1.x);
                        const unsigned long long a2 = pack2(v2.x, v2.x);
                        const unsigned long long a3 = pack2(v3.x, v3.x);
                        #pragma unroll
                        for (int p = 0; p < 9; p++) {
                            const unsigned long long w = wx[p];
                            ffma2(acc1[0][p], a0, w);
                            ffma2(acc1[1][p], a1, w);
                            ffma2(acc1[2][p], a2, w);
                            ffma2(acc1[3][p], a3, w);
                        }
                    }
                    {
                        const unsigned long long a0 = pack2(v0.y, v0.y);
                        const unsigned long long a1 = pack2(v1.y, v1.y);
                        const unsigned long long a2 = pack2(v2.y, v2.y);
                        const unsigned long long a3 = pack2(v3.y, v3.y);
                        #pragma unroll
                        for (int p = 0; p < 9; p++) {
                            const unsigned long long w = wy[p];
                            ffma2(acc1[0][p], a0, w);
                            ffma2(acc1[1][p], a1, w);
                            ffma2(acc1[2][p], a2, w);
                            ffma2(acc1[3][p], a3, w);
                        }
                    }
                }
            }
        }

        // cross-warp reduction
        __syncthreads();
        unsigned long long* red = (unsigned long long*)sm;

        if (q >= 4) {
            #pragma unroll
            for (int r = 0; r < 4; r++)
                #pragma unroll
                for (int p = 0; p < 9; p++)
                    red[((q - 4) * 128 + s + r*32) * 9 + p] = acc1[r][p];
        }
        __syncthreads();
        if (q < 4) {
            #pragma unroll
            for (int r = 0; r < 4; r++)
                #pragma unroll
                for (int p = 0; p < 9; p++)
                    addf2(acc1[r][p], red[(q * 128 + s + r*32) * 9 + p]);
        }
        __syncthreads();
        if (q == 2 || q == 3) {
            #pragma unroll
            for (int r = 0; r < 4; r++)
                #pragma unroll
                for (int p = 0; p < 9; p++)
                    red[((q - 2) * 128 + s + r*32) * 9 + p] = acc1[r][p];
        }
        __syncthreads();
        if (q < 2) {
            #pragma unroll
            for (int r = 0; r < 4; r++)
                #pragma unroll
                for (int p = 0; p < 9; p++)
                    addf2(acc1[r][p], red[(q * 128 + s + r*32) * 9 + p]);
        }
        __syncthreads();
        if (q == 1) {
            #pragma unroll
            for (int r = 0; r < 4; r++)
                #pragma unroll
                for (int p = 0; p < 9; p++)
                    red[(s + r*32) * 9 + p] = acc1[r][p];
        }
        __syncthreads();
        if (q == 0) {
            #pragma unroll
            for (int r = 0; r < 4; r++) {
                const int px = s + r*32;
                float2* op = (float2*)&g_offsets[(by * W_ + px) * 18];
                #pragma unroll
                for (int p = 0; p < 9; p++) {
                    addf2(acc1[r][p], red[px * 9 + p]);
                    float lo, hi;
                    asm("mov.b64 {%0,%1}, %2;" : "=f"(lo), "=f"(hi) : "l"(acc1[r][p]));
                    op[p] = make_float2(lo, hi);
                }
            }
        }
    }
    __syncthreads();   // offsets visible block-wide (global mem ordering)

    // ======================= PHASE 2: sampling + GEMM =======================
    {
        float* Abuf[2] = { sm, sm + ABUF2 };
        float* Bbuf[2] = { sm + 2*ABUF2, sm + 2*ABUF2 + BBUF };
        const uint32_t Bu = smem_u32(sm + 2*ABUF2);

        const int wid  = tid >> 5;
        const int lane = tid & 31;
        const int g  = lane >> 2;
        const int tc = lane & 3;

        const int p0 = by * 128;
        const int b  = p0 >> 14;
        const int y  = (p0 >> 7) & 127;
        const int pm = tid & 127;
        const int h  = tid >> 7;

        const int m_base = (wid >> 2) * 32;
        const int n_base = (wid & 3) * 32;
        const float* offp = &g_offsets[(p0 + pm) * 18];

        float acc[2][2][4][4];
        #pragma unroll
        for (int nf = 0; nf < 4; nf++) {
            const int c0 = n_base + nf*8 + 2*tc;
            const float bz0 = __ldg(&b_out[c0]), bz1 = __ldg(&b_out[c0+1]);
            #pragma unroll
            for (int sub = 0; sub < 2; sub++)
                #pragma unroll
                for (int mf = 0; mf < 2; mf++) {
                    acc[sub][mf][nf][0] = bz0; acc[sub][mf][nf][1] = bz1;
                    acc[sub][mf][nf][2] = bz0; acc[sub][mf][nf][3] = bz1;
                }
        }

        float wa=0.f, wbv=0.f, wcv=0.f, wdv=0.f;
        int i00=0, i10=0, i01=0, i11=0;

        #define COORDS(off) { \
            float nx = fminf(fmaxf((float)pm + (off).x, 0.f), 127.f); \
            float ny = fminf(fmaxf((float)y  + (off).y, 0.f), 127.f); \
            float x0f = floorf(nx), y0f = floorf(ny); \
            float x1f = fminf(x0f + 1.f, 127.f), y1f = fminf(y0f + 1.f, 127.f); \
            float lx = nx - x0f, hx = x1f - nx; \
            float ly = ny - y0f, hy = y1f - ny; \
            wa = hx*hy; wbv = hx*ly; wcv = lx*hy; wdv = lx*ly; \
            int ix0 = (int)x0f, ix1 = (int)x1f, iy0 = (int)y0f, iy1 = (int)y1f; \
            i00 = iy0*128 + ix0;  i10 = iy1*128 + ix0; \
            i01 = iy0*128 + ix1;  i11 = iy1*128 + ix1; }

        float4 ca, cb2, cc2, cd;

        #define GATHERPL(chv, j) { \
            const int cbp = (b*16 + ((chv)&1)*8 + h*4 + (j)) << 14; \
            ca  = g_xT[cbp + i00]; cb2 = g_xT[cbp + i10]; \
            cc2 = g_xT[cbp + i01]; cd  = g_xT[cbp + i11]; }

        #define WEIGHTSTS(j, Ab) { \
            const int kb = h*16 + (j)*4; \
            (Ab)[(kb+0)*SA3 + pm] = __uint_as_float(f2tf32(wa*ca.x + wbv*cb2.x + wcv*cc2.x + wdv*cd.x)); \
            (Ab)[(kb+1)*SA3 + pm] = __uint_as_float(f2tf32(wa*ca.y + wbv*cb2.y + wcv*cc2.y + wdv*cd.y)); \
            (Ab)[(kb+2)*SA3 + pm] = __uint_as_float(f2tf32(wa*ca.z + wbv*cb2.z + wcv*cc2.z + wdv*cd.z)); \
            (Ab)[(kb+3)*SA3 + pm] = __uint_as_float(f2tf32(wa*ca.w + wbv*cb2.w + wcv*cc2.w + wdv*cd.w)); }

        #define CPB(chv, pbuf) { \
            const uint32_t dbase = Bu + (uint32_t)(pbuf) * (BBUF*4u); \
            const char* srcb = (const char*)&g_wTp[(chv) * BBUF]; \
            _Pragma("unroll") \
            for (int i = 0; i < 5; i++) { \
                int idx = tid + i*256; \
                if (idx < 1088) cpasync16(dbase + (uint32_t)idx*16u, srcb + idx*16); \
            } }

        #define MMAS(sstep, Ab, Bb) { \
            const int k0 = (sstep) * 8; \
            const uint32_t* Br0 = (const uint32_t*)&(Bb)[(k0 + tc)     * SB]; \
            const uint32_t* Br1 = (const uint32_t*)&(Bb)[(k0 + tc + 4) * SB]; \
            uint32_t bfr[4][2]; \
            _Pragma("unroll") \
            for (int nf = 0; nf < 4; nf++) { \
                const int n = n_base + nf*8 + g; \
                bfr[nf][0] = Br0[n];  bfr[nf][1] = Br1[n]; \
            } \
            const uint32_t* Ar0 = (const uint32_t*)&(Ab)[(k0 + tc)     * SA3]; \
            const uint32_t* Ar1 = (const uint32_t*)&(Ab)[(k0 + tc + 4) * SA3]; \
            _Pragma("unroll") \
            for (int sub = 0; sub < 2; sub++) { \
                uint32_t afr[2][4]; \
                _Pragma("unroll") \
                for (int mf = 0; mf < 2; mf++) { \
                    const int m = sub*64 + m_base + mf*16 + g; \
                    afr[mf][0] = Ar0[m];  afr[mf][1] = Ar0[m+8]; \
                    afr[mf][2] = Ar1[m];  afr[mf][3] = Ar1[m+8]; \
                } \
                _Pragma("unroll") \
                for (int mf = 0; mf < 2; mf++) \
                    _Pragma("unroll") \
                    for (int nf = 0; nf < 4; nf++) \
                        mma_tf32(acc[sub][mf][nf], afr[mf], bfr[nf]); \
            } }

        float2 curoff  = *(const float2*)(offp + 0);
        float2 nextoff = *(const float2*)(offp + 2);
        COORDS(curoff);
        #pragma unroll
        for (int j = 0; j < 4; j++) {
            GATHERPL(0, j);
            WEIGHTSTS(j, Abuf[0]);
        }
        CPB(0, 0); CP_COMMIT();

        for (int ch = 0; ch < 18; ch++) {
            const int p = ch & 1;
            float* Ab = Abuf[p];
            float* Bb = Bbuf[p];
            float* An = Abuf[p ^ 1];

            CP_WAIT0();
            __syncthreads();

            const bool more = (ch + 1 < 18);
            if (more) {
                if (((ch + 1) & 1) == 0) {
                    COORDS(nextoff);
                    if (ch + 1 <= 14)
                        nextoff = *(const float2*)(offp + ((ch+3) >> 1) * 2);
                }
                GATHERPL(ch + 1, 0);
                CPB(ch + 1, p ^ 1); CP_COMMIT();
            }

            MMAS(0, Ab, Bb);
            if (more) { WEIGHTSTS(0, An); GATHERPL(ch + 1, 1); }
            MMAS(1, Ab, Bb);
            if (more) { WEIGHTSTS(1, An); GATHERPL(ch + 1, 2); }
            MMAS(2, Ab, Bb);
            if (more) { WEIGHTSTS(2, An); GATHERPL(ch + 1, 3); }
            MMAS(3, Ab, Bb);
            if (more) { WEIGHTSTS(3, An); }
        }

        #pragma unroll
        for (int sub = 0; sub < 2; sub++)
            #pragma unroll
            for (int mf = 0; mf < 2; mf++) {
                const int row = p0 + sub*64 + m_base + mf*16 + g;
                #pragma unroll
                for (int nf = 0; nf < 4; nf++) {
                    const int col = n_base + nf*8 + 2*tc;
                    *(float2*)&out[(size_t)row * F_ + col] =
                        make_float2(acc[sub][mf][nf][0], acc[sub][mf][nf][1]);
                    *(float2*)&out[(size_t)(row + 8) * F_ + col] =
                        make_float2(acc[sub][mf][nf][2], acc[sub][mf][nf][3]);
                }
            }
    }
}

// ---------------------------------------------------------------------------
extern "C" void kernel_launch(void* const* d_in, const int* in_sizes, int n_in,
                              void* d_out, int out_size)
{
    const float* x     = (const float*)d_in[0];
    const float* w_off = (const float*)d_in[1];
    const float* b_off = (const float*)d_in[2];
    const float* w_out = (const float*)d_in[3];
    const float* b_out = (const float*)d_in[4];
    float* out = (float*)d_out;

    cudaFuncSetAttribute(dconv_fused,
                         cudaFuncAttributeMaxDynamicSharedMemorySize, SM2_TOTAL);

    prep_fused <<<1353, 256>>>(w_out, w_off, (const float4*)x);
    dconv_fused<<<B_ * H_, 256, SM2_TOTAL>>>(x, b_off, b_out, out);
}